// round 16
// baseline (speedup 1.0000x reference)
#include <cuda_runtime.h>
#include <cuda_fp16.h>
#include <cstdint>

#define NB 64
#define NE 64
#define NC 64
#define NO 20

// ---------------- device scratch (no allocs allowed) ----------------
__device__ __align__(128) __half g_h1f[(size_t)NB*NE*196*NC];   // conv1 raw relu (fp16)
__device__ __align__(128) __half g_h2f[(size_t)NB*NE*49*NC];
__device__ __align__(128) __half g_h3f[(size_t)NB*NE*16*NC];
__device__ float g_feat[NB*NE*NC];
__device__ __align__(128) __half g_kBh[3][NB][9][64][64];  // scale-folded split weights hi [co][ci]
__device__ __align__(128) __half g_kBl[3][NB][9][64][64];  // lo
__device__ float g_C[3][NB][9][64];              // per-tap bias dot products
__device__ float g_sum[4*NC];
__device__ float g_sumsq[4*NC];

__device__ __forceinline__ uint32_t smem_u32(const void* p) {
    return (uint32_t)__cvta_generic_to_shared(p);
}
__device__ __forceinline__ uint32_t ph2(__half a, __half b) {
    unsigned short ua = *(unsigned short*)&a, ub = *(unsigned short*)&b;
    return (uint32_t)ua | ((uint32_t)ub << 16);
}

#define MMA_F16(acc, A0,A1,A2,A3, B0,B1) \
    asm volatile("mma.sync.aligned.m16n8k16.row.col.f32.f16.f16.f32 " \
        "{%0,%1,%2,%3}, {%4,%5,%6,%7}, {%8,%9}, {%0,%1,%2,%3};" \
        : "+f"(acc[0]),"+f"(acc[1]),"+f"(acc[2]),"+f"(acc[3]) \
        : "r"(A0),"r"(A1),"r"(A2),"r"(A3), "r"(B0),"r"(B1))

#define LDMATRIX_X4(r0,r1,r2,r3, addr) \
    asm volatile("ldmatrix.sync.aligned.m8n8.x4.shared.b16 {%0,%1,%2,%3}, [%4];" \
        : "=r"(r0),"=r"(r1),"=r"(r2),"=r"(r3) : "r"(addr))

#define LDS32(r, addr) \
    asm volatile("ld.shared.b32 %0, [%1];" : "=r"(r) : "r"(addr))

#define CP16(dst, src, sz) \
    asm volatile("cp.async.ca.shared.global [%0], [%1], 16, %2;" \
        :: "r"(dst), "l"(src), "r"(sz))
#define CP_COMMIT() asm volatile("cp.async.commit_group;")
#define CP_WAIT1()  asm volatile("cp.async.wait_group 1;")
#define CP_WAIT0()  asm volatile("cp.async.wait_group 0;")

// ---------------- zero stats + feat ----------------
__global__ void zero_kernel() {
    int i = blockIdx.x * 256 + threadIdx.x;
    if (i < 4*NC) { g_sum[i] = 0.f; g_sumsq[i] = 0.f; }
    if (i < NB*NE*NC) g_feat[i] = 0.f;
}

// ---------------- wprep: BN finalize (local) + transpose + scale fold + fp16 split + bias dots ----
__global__ __launch_bounds__(256) void wprep_kernel(const float* __restrict__ kw, int layer,
                                                    float invN) {
    __shared__ float s[64*65];
    __shared__ float s_C[64], s_sc[64], s_bb[64];
    int blk = blockIdx.x;
    int b = blk / 9, kk = blk - b*9;
    int t = threadIdx.x, lane = t & 31;
    if (t < 64) {
        float su = g_sum[layer*64 + t], q = g_sumsq[layer*64 + t];
        float m = su * invN;
        float v = q * invN - m*m;
        float sc = rsqrtf(v + 1e-3f);
        s_sc[t] = sc; s_bb[t] = -m * sc; s_C[t] = 0.f;
    }
    const float* src = kw + ((size_t)b*9 + kk)*4096;
    #pragma unroll
    for (int p = 0; p < 16; p++) {
        int idx = p*256 + t;           // = ci*64 + co
        int ci = idx >> 6, co = idx & 63;
        s[co*65 + ci] = src[idx];
    }
    __syncthreads();
    int ci = t & 63;
    float sc = s_sc[ci];
    float bb = s_bb[ci];
    __half* Dh = &g_kBh[layer][b][kk][0][0];
    __half* Dl = &g_kBl[layer][b][kk][0][0];
    #pragma unroll
    for (int e = 0; e < 16; e++) {
        int idx = e*256 + t;           // = co*64 + ci
        int co = idx >> 6;
        float w = s[co*65 + ci];
        float ws = w * sc;
        __half hi = __float2half(ws);
        __half lo = __float2half(ws - __half2float(hi));
        Dh[idx] = hi; Dl[idx] = lo;
        float c = bb * w;
        #pragma unroll
        for (int o = 16; o; o >>= 1) c += __shfl_down_sync(0xFFFFFFFFu, c, o);
        if (lane == 0) atomicAdd(&s_C[co], c);
    }
    __syncthreads();
    if (t < 64) g_C[layer][b][kk][t] = s_C[t];
}

// ---------------- conv1: Cin=1, 28x28 -> 14x14x64, fp16 output ----------------
__global__ __launch_bounds__(256) void conv1_kernel(const float* __restrict__ x,
                                                    const float* __restrict__ k1) {
    __shared__ float s_in[30*30];
    __shared__ float s_sum[NC];
    __shared__ float s_sq[NC];
    int be = blockIdx.x;
    int t = threadIdx.x;
    for (int i = t; i < 900; i += 256) s_in[i] = 0.f;
    if (t < NC) { s_sum[t] = 0.f; s_sq[t] = 0.f; }
    __syncthreads();
    const float* xp = x + (size_t)be * 784;
    for (int i = t; i < 784; i += 256) {
        int r = i / 28, c = i - r*28;
        s_in[(r+1)*30 + c + 1] = xp[i];
    }
    int cg = t & 15, ig = t >> 4;
    int b = be >> 6;
    float4 w[9];
    const float4* kp = (const float4*)(k1 + (size_t)b * 576);
    #pragma unroll
    for (int j = 0; j < 9; j++) w[j] = kp[j*16 + cg];
    __syncthreads();
    float ls0=0,ls1=0,ls2=0,ls3=0, lq0=0,lq1=0,lq2=0,lq3=0;
    __half* of = g_h1f + (size_t)be * 196 * 64;
    for (int p = ig; p < 196; p += 16) {
        int oy = p / 14, ox = p - oy*14;
        float a0=0,a1=0,a2=0,a3=0;
        #pragma unroll
        for (int ky = 0; ky < 3; ky++)
        #pragma unroll
        for (int kx = 0; kx < 3; kx++) {
            float v = s_in[(2*oy+ky)*30 + 2*ox + kx];
            float4 ww = w[ky*3+kx];
            a0 = fmaf(v, ww.x, a0); a1 = fmaf(v, ww.y, a1);
            a2 = fmaf(v, ww.z, a2); a3 = fmaf(v, ww.w, a3);
        }
        a0 = fmaxf(a0, 0.f); a1 = fmaxf(a1, 0.f);
        a2 = fmaxf(a2, 0.f); a3 = fmaxf(a3, 0.f);
        ls0+=a0; ls1+=a1; ls2+=a2; ls3+=a3;
        lq0+=a0*a0; lq1+=a1*a1; lq2+=a2*a2; lq3+=a3*a3;
        ((uint2*)(of + p*64))[cg] =
            make_uint2(ph2(__float2half(a0), __float2half(a1)),
                       ph2(__float2half(a2), __float2half(a3)));
    }
    int co4 = cg*4;
    atomicAdd(&s_sum[co4+0], ls0); atomicAdd(&s_sum[co4+1], ls1);
    atomicAdd(&s_sum[co4+2], ls2); atomicAdd(&s_sum[co4+3], ls3);
    atomicAdd(&s_sq[co4+0], lq0); atomicAdd(&s_sq[co4+1], lq1);
    atomicAdd(&s_sq[co4+2], lq2); atomicAdd(&s_sq[co4+3], lq3);
    __syncthreads();
    if (t < NC) {
        atomicAdd(&g_sum[t], s_sum[t]);
        atomicAdd(&g_sumsq[t], s_sq[t]);
    }
}

// ---------------- conv layers 2-4: M-tile 128, warps m32xn32, cp.async 2-stage ----------------
// 8 warps = 4 m32-quarters x 2 n32-halves. Each B fragment feeds 2 MMAs (m reuse).
template<int LNUM>
__global__ __launch_bounds__(256, 2) void conv_kernel() {
    constexpr int HIN  = (LNUM==1) ? 14 : (LNUM==2) ? 7 : 4;
    constexpr int HOUT = (LNUM==1) ? 7  : (LNUM==2) ? 4 : 2;
    constexpr bool LAST = (LNUM==3);
    constexpr int POS   = HOUT*HOUT;
    constexpr int MTASK = NE*POS;
    constexpr int RS    = 144;
    constexpr int A_O = 0, B_HI = 128*RS, B_LO = 192*RS;
    constexpr int STAGE = 256*RS;        // 36864
    constexpr int BIAS_O = 2*STAGE;

    __shared__ float s_sum[64], s_sq[64];
    __shared__ int s_ri[128];
    extern __shared__ char dsm[];
    float* s_bias = (float*)(dsm + BIAS_O);

    int b = blockIdx.y, m0 = blockIdx.x*128, t = threadIdx.x;
    int wid = t >> 5, lane = t & 31;

    if (t < 64) { s_sum[t] = 0.f; s_sq[t] = 0.f; }
    if (t < 128) {
        int gic = min(m0 + t, MTASK-1);
        int e = gic / POS, p = gic - e*POS;
        s_ri[t] = (e << 16) | ((p / HOUT) << 8) | (p % HOUT);
    }
    {
        const float* Cb = &g_C[LNUM-1][b][0][0];
        for (int idx = t; idx < POS*64; idx += 256) {
            int p = idx >> 6, co = idx & 63;
            int oy = p / HOUT, ox = p - oy*HOUT;
            float s = 0.f;
            #pragma unroll
            for (int ky = 0; ky < 3; ky++) {
                int iy = 2*oy - 1 + ky;
                if ((unsigned)iy >= (unsigned)HIN) continue;
                #pragma unroll
                for (int kx = 0; kx < 3; kx++) {
                    int ix = 2*ox - 1 + kx;
                    if ((unsigned)ix < (unsigned)HIN) s += Cb[(ky*3+kx)*64 + co];
                }
            }
            s_bias[idx] = s;
        }
    }
    __syncthreads();

    const __half* pa = ((LNUM==1) ? g_h1f : (LNUM==2) ? g_h2f : g_h3f)
                     + (size_t)b*NE*HIN*HIN*64;
    __half* of = (LNUM==1) ? g_h2f : g_h3f;
    const char* pac = (const char*)pa;
    const char* Bhc = (const char*)&g_kBh[LNUM-1][b][0][0][0];
    const char* Blc = (const char*)&g_kBl[LNUM-1][b][0][0][0];

    // loader: seg = t&7 (16B col chunk), rb = t>>3 (0..31); A rows rb+{0,32,64,96},
    // B rows rb and rb+32 for hi and lo planes.
    int seg = t & 7, rb = t >> 3;
    int abA[4], iybA[4], ixbA[4];
    uint32_t dA[4];
    #pragma unroll
    for (int j = 0; j < 4; j++) {
        int row = rb + j*32;
        int inf = s_ri[row];
        int e = inf >> 16;
        iybA[j] = 2*((inf >> 8) & 255) - 1;
        ixbA[j] = 2*(inf & 255) - 1;
        abA[j] = e*HIN*HIN*128 + seg*16;
        dA[j] = A_O + row*RS + seg*16;
    }
    uint32_t dB0 = B_HI + rb*RS + seg*16, dB1 = B_HI + (rb+32)*RS + seg*16;
    int rbB0 = rb*128 + seg*16, rbB1 = (rb+32)*128 + seg*16;

    uint32_t smem0 = smem_u32(dsm);

    auto issue = [&](int kk, uint32_t sb) {
        int ky = kk/3, kx = kk - (kk/3)*3;
        #pragma unroll
        for (int j = 0; j < 4; j++) {
            int iy = iybA[j] + ky, ix = ixbA[j] + kx;
            bool v = (unsigned)iy < (unsigned)HIN && (unsigned)ix < (unsigned)HIN;
            int o = v ? (abA[j] + (iy*HIN + ix)*128) : 0;
            CP16(sb + dA[j], pac + o, v ? 16 : 0);
        }
        int bo = kk*8192;
        CP16(sb + dB0,                 Bhc + bo + rbB0, 16);
        CP16(sb + dB1,                 Bhc + bo + rbB1, 16);
        CP16(sb + dB0 + (B_LO - B_HI), Blc + bo + rbB0, 16);
        CP16(sb + dB1 + (B_LO - B_HI), Blc + bo + rbB1, 16);
    };

    int mw = wid & 3, nh = wid >> 2;     // m32-quarter, n32-half
    float acc[2][4][4];
    #pragma unroll
    for (int mt = 0; mt < 2; mt++)
        #pragma unroll
        for (int nt = 0; nt < 4; nt++)
            #pragma unroll
            for (int j = 0; j < 4; j++) acc[mt][nt][j] = 0.f;

    auto domma = [&](uint32_t sb) {
        uint32_t a_base0 = sb + A_O + (mw*32)*RS + (lane & 15)*RS + ((lane >> 4) * 16);
        uint32_t a_base1 = a_base0 + 16*RS;
        uint32_t b_base = sb + B_HI + (nh*32 + (lane >> 2))*RS + (lane & 3)*4;
        #pragma unroll
        for (int ks = 0; ks < 4; ks++) {
            uint32_t a00,a01,a02,a03, a10,a11,a12,a13;
            LDMATRIX_X4(a00,a01,a02,a03, a_base0 + ks*32);
            LDMATRIX_X4(a10,a11,a12,a13, a_base1 + ks*32);
            #pragma unroll
            for (int nt = 0; nt < 4; nt++) {
                uint32_t ba = b_base + nt*(8*RS) + ks*32;
                uint32_t bh0,bh1,bl0,bl1;
                LDS32(bh0, ba);
                LDS32(bh1, ba + 16);
                LDS32(bl0, ba + (B_LO - B_HI));
                LDS32(bl1, ba + (B_LO - B_HI) + 16);
                MMA_F16(acc[0][nt], a00,a01,a02,a03, bh0,bh1);
                MMA_F16(acc[0][nt], a00,a01,a02,a03, bl0,bl1);
                MMA_F16(acc[1][nt], a10,a11,a12,a13, bh0,bh1);
                MMA_F16(acc[1][nt], a10,a11,a12,a13, bl0,bl1);
            }
        }
    };

    // ---- 2-stage pipeline over 9 chunks ----
    issue(0, smem0);
    CP_COMMIT();
    #pragma unroll
    for (int kk = 0; kk < 9; kk++) {
        if (kk < 8) {
            issue(kk+1, smem0 + ((kk+1) & 1)*STAGE);
            CP_COMMIT();
            CP_WAIT1();
        } else {
            CP_WAIT0();
        }
        __syncthreads();
        domma(smem0 + (kk & 1)*STAGE);
        __syncthreads();
    }

    // ---- epilogue: +bias, relu, stats, fp16 store / max-pool ----
    int q = lane & 3, r = lane >> 2;
    float lsum[8], lsq[8];
    #pragma unroll
    for (int j = 0; j < 8; j++) { lsum[j] = 0.f; lsq[j] = 0.f; }
    #pragma unroll
    for (int mt = 0; mt < 2; mt++) {
        int g0 = m0 + mw*32 + mt*16 + r, g1 = g0 + 8;
        bool v0 = g0 < MTASK, v1 = g1 < MTASK;
        int E0 = g0 / POS, p0 = g0 - E0*POS;
        int E1 = g1 / POS, p1 = g1 - E1*POS;
        #pragma unroll
        for (int nt = 0; nt < 4; nt++) {
            int col = (nh*4 + nt)*8 + q*2;
            float d0 = v0 ? fmaxf(acc[mt][nt][0] + s_bias[p0*64+col],   0.f) : 0.f;
            float d1 = v0 ? fmaxf(acc[mt][nt][1] + s_bias[p0*64+col+1], 0.f) : 0.f;
            float d2 = v1 ? fmaxf(acc[mt][nt][2] + s_bias[p1*64+col],   0.f) : 0.f;
            float d3 = v1 ? fmaxf(acc[mt][nt][3] + s_bias[p1*64+col+1], 0.f) : 0.f;
            lsum[2*nt]   += d0 + d2;  lsq[2*nt]   += d0*d0 + d2*d2;
            lsum[2*nt+1] += d1 + d3;  lsq[2*nt+1] += d1*d1 + d3*d3;
            if (!LAST) {
                if (v0) *(uint32_t*)(of + ((size_t)b*MTASK + g0)*64 + col) =
                            ph2(__float2half(d0), __float2half(d1));
                if (v1) *(uint32_t*)(of + ((size_t)b*MTASK + g1)*64 + col) =
                            ph2(__float2half(d2), __float2half(d3));
            } else {
                if (v0) {
                    int* fp = (int*)(g_feat + (size_t)(b*NE + E0)*64 + col);
                    atomicMax(&fp[0], __float_as_int(d0));
                    atomicMax(&fp[1], __float_as_int(d1));
                }
                if (v1) {
                    int* fp = (int*)(g_feat + (size_t)(b*NE + E1)*64 + col);
                    atomicMax(&fp[0], __float_as_int(d2));
                    atomicMax(&fp[1], __float_as_int(d3));
                }
            }
        }
    }
    #pragma unroll
    for (int j = 0; j < 8; j++) {
        #pragma unroll
        for (int o = 4; o <= 16; o <<= 1) {
            lsum[j] += __shfl_xor_sync(0xFFFFFFFFu, lsum[j], o);
            lsq[j]  += __shfl_xor_sync(0xFFFFFFFFu, lsq[j],  o);
        }
    }
    if (lane < 4) {
        #pragma unroll
        for (int nt = 0; nt < 4; nt++) {
            int col = (nh*4 + nt)*8 + lane*2;
            atomicAdd(&s_sum[col],   lsum[2*nt]);
            atomicAdd(&s_sum[col+1], lsum[2*nt+1]);
            atomicAdd(&s_sq[col],    lsq[2*nt]);
            atomicAdd(&s_sq[col+1],  lsq[2*nt+1]);
        }
    }
    __syncthreads();
    if (t < 64) {
        atomicAdd(&g_sum[LNUM*NC + t],   s_sum[t]);
        atomicAdd(&g_sumsq[LNUM*NC + t], s_sq[t]);
    }
}

// ---------------- readout: local BN finalize, normalize pooled feats, per-task matmul ----
__global__ __launch_bounds__(256) void readout_kernel(const float* __restrict__ w_ro,
                                                      float* __restrict__ out, float invN) {
    __shared__ float s_w[64*20];
    __shared__ float s_f[64*64];
    __shared__ float s_sc[64], s_bi[64];
    int b = blockIdx.x, t = threadIdx.x;
    if (t < 64) {
        float su = g_sum[192 + t], q = g_sumsq[192 + t];
        float m = su * invN;
        float v = q * invN - m*m;
        float sc = rsqrtf(v + 1e-3f);
        s_sc[t] = sc; s_bi[t] = -m * sc;
    }
    for (int i = t; i < 1280; i += 256) s_w[i] = w_ro[(size_t)b*1280 + i];
    __syncthreads();
    const float* fp = g_feat + (size_t)b*4096;
    for (int i = t; i < 4096; i += 256) {
        int c = i & 63;
        s_f[i] = fmaf(fp[i], s_sc[c], s_bi[c]);
    }
    __syncthreads();
    for (int idx = t; idx < 1280; idx += 256) {
        int e = idx/20, o = idx - e*20;
        float s = 0.f;
        const float* fe = s_f + e*64;
        #pragma unroll 16
        for (int c = 0; c < 64; c++) s = fmaf(fe[c], s_w[c*20+o], s);
        out[(size_t)b*1280 + idx] = s;
    }
}

// ---------------- launch ----------------
extern "C" void kernel_launch(void* const* d_in, const int* in_sizes, int n_in,
                              void* d_out, int out_size) {
    const float* x  = (const float*)d_in[0];
    const float* k1 = (const float*)d_in[1];
    const float* k2 = (const float*)d_in[2];
    const float* k3 = (const float*)d_in[3];
    const float* k4 = (const float*)d_in[4];
    const float* w  = (const float*)d_in[5];
    float* out = (float*)d_out;
    (void)in_sizes; (void)n_in; (void)out_size;

    const int STAGE2 = 2*256*144;                  // 73728
    const int dsm1 = STAGE2 + 49*64*4;             // 86272
    const int dsm2 = STAGE2 + 16*64*4;             // 77824
    const int dsm3 = STAGE2 + 4*64*4;              // 74752
    cudaFuncSetAttribute(conv_kernel<1>, cudaFuncAttributeMaxDynamicSharedMemorySize, dsm1);
    cudaFuncSetAttribute(conv_kernel<2>, cudaFuncAttributeMaxDynamicSharedMemorySize, dsm2);
    cudaFuncSetAttribute(conv_kernel<3>, cudaFuncAttributeMaxDynamicSharedMemorySize, dsm3);

    zero_kernel<<<1024, 256>>>();
    conv1_kernel<<<NB*NE, 256>>>(x, k1);
    wprep_kernel<<<576, 256>>>(k2, 0, 1.f/(NB*NE*196.f));
    conv_kernel<1><<<dim3(25, NB), 256, dsm1>>>();
    wprep_kernel<<<576, 256>>>(k3, 1, 1.f/(NB*NE*49.f));
    conv_kernel<2><<<dim3(8, NB), 256, dsm2>>>();
    wprep_kernel<<<576, 256>>>(k4, 2, 1.f/(NB*NE*16.f));
    conv_kernel<3><<<dim3(2, NB), 256, dsm3>>>();
    readout_kernel<<<NB, 256>>>(w, out, 1.f/(NB*NE*4.f));
}